// round 13
// baseline (speedup 1.0000x reference)
#include <cuda_runtime.h>
#include <cuda_bf16.h>
#include <cuda_pipeline.h>
#include <math.h>

// Problem constants
#define PB 32
#define PN 4096
#define PD 768
#define PC 10
#define PK 16
#define NPROD (PB * PN / 8)      // 16384 producer CTAs (8 rows each)

// Scratch
__device__ unsigned g_scores_u[PB * PN];   // pre-flipped monotone scores
__device__ unsigned g_cnt[PB];             // per-batch producer-CTA arrival count (reset by consumer)

// Monotone 32-bit mapping: flip(a) > flip(b)  <=>  a > b (as floats)
__device__ __forceinline__ unsigned flip_f32(float s) {
    unsigned u = __float_as_uint(s);
    return (u & 0x80000000u) ? ~u : (u | 0x80000000u);
}

// ---------------------------------------------------------------------------
// Fused kernel: 16384 producer CTAs (scores, at HBM roofline) + 32 consumer
// CTAs (per-batch top-16 + A scatter + gather/mean + classifier) that
// spin-wait on per-batch counters so their latency hides under the producers.
// ---------------------------------------------------------------------------
__global__ void __launch_bounds__(256) fused_mil_kernel(
    const float* __restrict__ H,
    const float* __restrict__ w_score,
    const float* __restrict__ b_score,
    const float* __restrict__ W_cls,    // [D, C] row-major
    const float* __restrict__ b_cls,    // [C]
    float* __restrict__ logits_out,     // d_out, size PB*PC
    float* __restrict__ A_out)          // d_out + PB*PC, size PB*PN
{
    const int bid  = blockIdx.x;
    const int tid  = threadIdx.x;
    const int warp = tid >> 5;
    const int lane = tid & 31;
    const unsigned FULL = 0xFFFFFFFFu;
    const unsigned BIGI = 0xFFFFFFFFu;

    if (bid < NPROD) {
        // ================= PRODUCER: 8 rows, one warp each =================
        // Zero this CTA's 8 A entries (same batch region its counter covers).
        if (tid < 8) A_out[bid * 8 + tid] = 0.0f;

        const int row = bid * 8 + warp;
        const float4* __restrict__ h4 = (const float4*)(H + (size_t)row * PD);
        const float4* __restrict__ w4 = (const float4*)w_score;

        float sum = 0.0f;
        #pragma unroll
        for (int k = 0; k < PD / 128; k++) {          // 6 float4 per lane
            float4 a = __ldcs(&h4[lane + k * 32]);    // streaming: evict-first
            float4 b = __ldg(&w4[lane + k * 32]);
            sum += a.x * b.x + a.y * b.y + a.z * b.z + a.w * b.w;
        }
        #pragma unroll
        for (int o = 16; o > 0; o >>= 1)
            sum += __shfl_down_sync(FULL, sum, o);

        if (lane == 0) g_scores_u[row] = flip_f32(sum + b_score[0]);

        // Publish: all stores visible, then one arrival per CTA.
        __threadfence();
        __syncthreads();
        if (tid == 0) atomicAdd(&g_cnt[bid >> 9], 1u);   // 512 CTAs per batch
        return;
    }

    // ==================== CONSUMER: one CTA per batch ====================
    const int b = bid - NPROD;

    __shared__ __align__(16) float sW[PD * PC];   // 30720 B
    __shared__ unsigned cand_v[8 * PK];
    __shared__ unsigned cand_i[8 * PK];
    __shared__ int top[PK];
    __shared__ float partial[8][PC];

    // W_cls -> smem prefetch, overlapped with the wait.
    {
        const float4* __restrict__ Wg = (const float4*)W_cls;
        float4* Ws = (float4*)sW;
        #pragma unroll
        for (int i = 0; i < 8; i++) {
            int idx = tid + i * 256;
            if (idx < (PD * PC) / 4)
                __pipeline_memcpy_async(&Ws[idx], &Wg[idx], 16);
        }
        __pipeline_commit();
    }

    // Wait for this batch's 512 producer CTAs.
    if (tid == 0) {
        while (atomicAdd(&g_cnt[b], 0u) < 512u) __nanosleep(128);
    }
    __syncthreads();
    __threadfence();   // acquire ordering before reading scores

    // ---- Phase 1: per-warp top-16 over 512 scores (16 u32 regs/lane) ----
    {
        unsigned kv[16];
        const unsigned* __restrict__ sb = g_scores_u + b * PN + warp * 512;
        #pragma unroll
        for (int j = 0; j < 16; j++)
            kv[j] = sb[j * 32 + lane];                 // coalesced, L2-fresh
        const unsigned base = (unsigned)(warp * 512 + lane);

        #pragma unroll
        for (int it = 0; it < PK; it++) {
            unsigned bv = kv[0]; unsigned bj = 0;
            #pragma unroll
            for (int j = 1; j < 16; j++)
                if (kv[j] > bv) { bv = kv[j]; bj = (unsigned)j; }
            unsigned mx = __reduce_max_sync(FULL, bv);
            unsigned my = (bv == mx) ? (base + bj * 32) : BIGI;
            unsigned wi = __reduce_min_sync(FULL, my);
            unsigned r  = wi - base;                   // == j*32 iff my slot won
            #pragma unroll
            for (int j = 0; j < 16; j++)
                if (r == (unsigned)(j * 32)) kv[j] = 0u;
            if (lane == 0) { cand_v[warp * PK + it] = mx; cand_i[warp * PK + it] = wi; }
        }
    }
    __syncthreads();

    // ---- Phase 2: warp 0 merges 128 candidates -> global top-16 ----
    if (warp == 0) {
        unsigned vv[4], vi[4];
        #pragma unroll
        for (int j = 0; j < 4; j++) {
            vv[j] = cand_v[j * 32 + lane];
            vi[j] = cand_i[j * 32 + lane];
        }
        #pragma unroll
        for (int it = 0; it < PK; it++) {
            unsigned bv = vv[0], bi = vi[0];
            #pragma unroll
            for (int j = 1; j < 4; j++) {
                bool better = (vv[j] > bv) || (vv[j] == bv && vi[j] < bi);
                if (better) { bv = vv[j]; bi = vi[j]; }
            }
            unsigned mx = __reduce_max_sync(FULL, bv);
            unsigned my = (bv == mx) ? bi : BIGI;
            unsigned wi = __reduce_min_sync(FULL, my);
            #pragma unroll
            for (int j = 0; j < 4; j++)
                if (vv[j] == mx && vi[j] == wi) { vv[j] = 0u; vi[j] = BIGI; }
            if (lane == 0) top[it] = (int)wi;
        }
    }
    __pipeline_wait_prior(0);
    __syncthreads();

    // ---- Scatter attention mask A (A zeros published by this batch's producers) ----
    if (tid < PK) A_out[b * PN + top[tid]] = 1.0f / (float)PK;

    // ---- Gather + mean (all 8 warps, 24 lanes x float4) + partial GEMV ----
    const float4* __restrict__ H4 = (const float4*)H;
    float4 m = make_float4(0.f, 0.f, 0.f, 0.f);
    const int d4 = warp * 24 + ((lane < 24) ? lane : 23);   // clamped, in-bounds
    if (lane < 24) {
        #pragma unroll
        for (int j = 0; j < PK; j++) {
            float4 h = __ldcs(&H4[((size_t)b * PN + top[j]) * (PD / 4) + d4]);
            m.x += h.x; m.y += h.y; m.z += h.z; m.w += h.w;
        }
        const float inv = 1.0f / (float)PK;
        m.x *= inv; m.y *= inv; m.z *= inv; m.w *= inv;
    }
    float p[PC];
    #pragma unroll
    for (int c = 0; c < PC; c++) {
        const float* w0 = sW + (d4 * 4) * PC + c;
        p[c] = m.x * w0[0] + m.y * w0[PC] + m.z * w0[2 * PC] + m.w * w0[3 * PC];
    }
    #pragma unroll
    for (int c = 0; c < PC; c++) {
        #pragma unroll
        for (int o = 16; o > 0; o >>= 1)
            p[c] += __shfl_xor_sync(FULL, p[c], o);
    }
    if (lane == 0) {
        #pragma unroll
        for (int c = 0; c < PC; c++) partial[warp][c] = p[c];
    }
    __syncthreads();

    // ---- Final logits ----
    if (tid < PC) {
        float acc = b_cls[tid];
        #pragma unroll
        for (int w = 0; w < 8; w++) acc += partial[w][tid];
        logits_out[b * PC + tid] = acc;
    }

    // ---- Reset this batch's counter for the next graph replay ----
    __syncthreads();
    if (tid == 0) atomicExch(&g_cnt[b], 0u);
}

// ---------------------------------------------------------------------------
// Launch: single fused kernel, 16384 producer CTAs + 32 consumer CTAs.
// Inputs (metadata order): H [B,N,D] f32, w_score [D] f32, b_score [] f32,
//                          W_cls [D,C] f32, b_cls [C] f32.
// Output: logits [B,C] (320 floats) followed by A [B,N,1] (131072 floats).
// ---------------------------------------------------------------------------
extern "C" void kernel_launch(void* const* d_in, const int* in_sizes, int n_in,
                              void* d_out, int out_size)
{
    const float* H       = (const float*)d_in[0];
    const float* w_score = (const float*)d_in[1];
    const float* b_score = (const float*)d_in[2];
    const float* W_cls   = (const float*)d_in[3];
    const float* b_cls   = (const float*)d_in[4];

    float* logits_out = (float*)d_out;
    float* A_out      = (float*)d_out + PB * PC;

    fused_mil_kernel<<<NPROD + PB, 256>>>(H, w_score, b_score,
                                          W_cls, b_cls, logits_out, A_out);
}